// round 11
// baseline (speedup 1.0000x reference)
#include <cuda_runtime.h>
#include <cstdint>

#define TT 2048
#define BB 128
#define HH 200
#define HP 208        // padded neuron count
#define KH 100        // k-half span

typedef unsigned long long ull;

__device__ __forceinline__ void fma2(ull& acc, ull a, ull b) {
    asm("fma.rn.f32x2 %0, %1, %2, %0;" : "+l"(acc) : "l"(a), "l"(b));
}
__device__ __forceinline__ void unpack2(ull v, float& lo, float& hi) {
    asm("mov.b64 {%0,%1}, %2;" : "=f"(lo), "=f"(hi) : "l"(v));
}
__device__ __forceinline__ float tanh_hw(float x) {
    float r; asm("tanh.approx.f32 %0, %1;" : "=f"(r) : "f"(x));
    return r;
}

// 448 threads = 14 warps; ONE CTA handles TWO batch rows (b0, b1).
//  tid < 416: compute. j = tid>>1 (0..207; j>=200 zero pads), kh = tid&1.
//    Thread holds W_hh[j, 100kh : +100) once (50 u64) and runs TWO accumulator
//    sets, one per batch; chains interleave to fill latency edges.
//  warp 13: output head for both batches, step t-1, overlapped with compute.
// Double-buffered h per batch => one __syncthreads per step.
__global__ void __launch_bounds__(448, 1) rnn_kernel(
    const float* __restrict__ x,     // [T, B, 2]
    const float* __restrict__ Wih,   // [H, 2]
    const float* __restrict__ Whh,   // [H, H]
    const float* __restrict__ bih,   // [H]
    const float* __restrict__ bhh,   // [H]
    const float* __restrict__ Wout,  // [1, H]
    const float* __restrict__ bOut,  // [1]
    float* __restrict__ out)         // [T, B, 1]
{
    __shared__ __align__(16) float2 xsmA[TT];       // batch b0 inputs (16 KB)
    __shared__ __align__(16) float2 xsmB[TT];       // batch b1 inputs (16 KB)
    __shared__ __align__(16) float  hsmA[2][HP];    // b0 hidden, double-buffered
    __shared__ __align__(16) float  hsmB[2][HP];    // b1 hidden, double-buffered
    __shared__ __align__(16) float  houtA[2][HP];   // b0 h parity buffers (head)
    __shared__ __align__(16) float  houtB[2][HP];   // b1 h parity buffers (head)

    const int tid  = threadIdx.x;
    const int b0   = 2 * blockIdx.x;
    const int b1   = b0 + 1;
    const int lane = tid & 31;
    const int j    = tid >> 1;
    const int kh   = tid & 1;
    const bool compute = (tid < 416);
    const bool valid   = compute && (j < HH);
    const bool even    = (kh == 0);

    // Preload both batches' input sequences
    for (int i = tid; i < TT; i += 448) {
        xsmA[i] = *(const float2*)(x + ((size_t)i * BB + b0) * 2);
        xsmB[i] = *(const float2*)(x + ((size_t)i * BB + b1) * 2);
    }

    // W_hh[j, kh*100 : +100) as 50 packed fp32 pairs — shared by both batches
    ull wr[50];
    {
        const ull* wrow = (const ull*)(Whh + (size_t)j * HH + kh * KH);
#pragma unroll
        for (int i = 0; i < 50; i++) wr[i] = valid ? wrow[i] : 0ull;
    }

    float wih0 = 0.f, wih1 = 0.f, bias = 0.f;
    if (valid) {
        wih0 = Wih[2 * j];
        wih1 = Wih[2 * j + 1];
        bias = bih[j] + bhh[j];
    }
    // Out-warp constants
    float wo[7];
    if (!compute) {
#pragma unroll
        for (int i = 0; i < 7; i++) {
            int idx = lane + 32 * i;
            wo[i] = (idx < HH) ? Wout[idx] : 0.0f;
        }
    }
    const float bo = bOut[0];

    // h_0 = 0 for both batches (pads included)
    for (int i = tid; i < 2 * HP; i += 448) {
        ((float*)hsmA)[i] = 0.0f;
        ((float*)hsmB)[i] = 0.0f;
    }
    __syncthreads();

    auto step = [&](int t, int rp) {
        if (compute) {
            const ulonglong2* hpA = (const ulonglong2*)(&hsmA[rp][kh * KH]);
            const ulonglong2* hpB = (const ulonglong2*)(&hsmB[rp][kh * KH]);
            ull aA0 = 0ull, aA1 = 0ull, aB0 = 0ull, aB1 = 0ull;
#pragma unroll
            for (int i = 0; i < 25; i++) {
                ulonglong2 hvA = hpA[i];
                ulonglong2 hvB = hpB[i];
                fma2(aA0, hvA.x, wr[2 * i]);
                fma2(aA1, hvA.y, wr[2 * i + 1]);
                fma2(aB0, hvB.x, wr[2 * i]);
                fma2(aB1, hvB.y, wr[2 * i + 1]);
            }
            float u0, u1, u2, u3, v0, v1, v2, v3;
            unpack2(aA0, u0, u1); unpack2(aA1, u2, u3);
            unpack2(aB0, v0, v1); unpack2(aB1, v2, v3);
            float sA = (u0 + u1) + (u2 + u3);
            float sB = (v0 + v1) + (v2 + v3);
            sA += __shfl_xor_sync(0xFFFFFFFFu, sA, 1);   // combine k-halves
            sB += __shfl_xor_sync(0xFFFFFFFFu, sB, 1);
            float2 xvA = xsmA[t];
            float2 xvB = xsmB[t];
            float hA = tanh_hw(fmaf(xvA.x, wih0, fmaf(xvA.y, wih1, sA + bias)));
            float hB = tanh_hw(fmaf(xvB.x, wih0, fmaf(xvB.y, wih1, sB + bias)));
            if (even) {                                   // one writer per neuron
                hsmA[rp ^ 1][j] = hA;
                hsmB[rp ^ 1][j] = hB;
                houtA[t & 1][j] = hA;
                houtB[t & 1][j] = hB;
            }
        } else if (t > 0) {
            // warp 13: head for step t-1, both batches (overlapped with compute)
            const float* hvA = houtA[(t - 1) & 1];
            const float* hvB = houtB[(t - 1) & 1];
            float accA = 0.0f, accB = 0.0f;
#pragma unroll
            for (int i = 0; i < 7; i++) {
                int idx = lane + 32 * i;
                if (idx < HH) {
                    accA = fmaf(hvA[idx], wo[i], accA);
                    accB = fmaf(hvB[idx], wo[i], accB);
                }
            }
#pragma unroll
            for (int off = 16; off; off >>= 1) {
                accA += __shfl_xor_sync(0xFFFFFFFFu, accA, off);
                accB += __shfl_xor_sync(0xFFFFFFFFu, accB, off);
            }
            if (lane == 0) {
                out[(size_t)(t - 1) * BB + b0] = accA + bo;
                out[(size_t)(t - 1) * BB + b1] = accB + bo;
            }
        }
        __syncthreads();
    };

#pragma unroll 1
    for (int t = 0; t < TT; t += 2) {
        step(t, 0);
        step(t + 1, 1);
    }

    // Final step's head outputs (t = TT-1, parity 1)
    if (!compute) {
        const float* hvA = houtA[1];
        const float* hvB = houtB[1];
        float accA = 0.0f, accB = 0.0f;
#pragma unroll
        for (int i = 0; i < 7; i++) {
            int idx = lane + 32 * i;
            if (idx < HH) {
                accA = fmaf(hvA[idx], wo[i], accA);
                accB = fmaf(hvB[idx], wo[i], accB);
            }
        }
#pragma unroll
        for (int off = 16; off; off >>= 1) {
            accA += __shfl_xor_sync(0xFFFFFFFFu, accA, off);
            accB += __shfl_xor_sync(0xFFFFFFFFu, accB, off);
        }
        if (lane == 0) {
            out[(size_t)(TT - 1) * BB + b0] = accA + bo;
            out[(size_t)(TT - 1) * BB + b1] = accB + bo;
        }
    }
}

extern "C" void kernel_launch(void* const* d_in, const int* in_sizes, int n_in,
                              void* d_out, int out_size) {
    const float* input_seq = (const float*)d_in[0];  // [T,B,2]
    const float* W_ih      = (const float*)d_in[1];  // [H,2]
    const float* W_hh      = (const float*)d_in[2];  // [H,H]
    const float* b_ih      = (const float*)d_in[3];  // [H]
    const float* b_hh      = (const float*)d_in[4];  // [H]
    const float* W_out     = (const float*)d_in[5];  // [1,H]
    const float* b_out     = (const float*)d_in[6];  // [1]
    float* out = (float*)d_out;                      // [T,B,1]

    rnn_kernel<<<BB / 2, 448>>>(input_seq, W_ih, W_hh, b_ih, b_hh,
                                W_out, b_out, out);
}